// round 1
// baseline (speedup 1.0000x reference)
#include <cuda_runtime.h>

#define NDET      5000
#define TOPK      1000
#define NCLS      80
#define DETSTRIDE 84
#define CH        256
#define CROP      14

// Scratch (no allocations allowed in kernel_launch)
__device__ float g_scores[NDET];
__device__ int   g_sel[TOPK];            // rank -> original detection row
__device__ float g_rank_boxes[TOPK][4];  // boxes ordered by top-k rank
__device__ int   g_rank_level[TOPK];
__device__ float g_boxes[TOPK][4];       // boxes after stable level sort
__device__ int   g_level[TOPK];

// ---------------------------------------------------------------------------
// K1: per-row max over 80 class scores
// ---------------------------------------------------------------------------
__global__ void k_scores(const float* __restrict__ det) {
    int r = blockIdx.x * blockDim.x + threadIdx.x;
    if (r >= NDET) return;
    const float* p = det + r * DETSTRIDE + 4;
    float m = p[0];
#pragma unroll 8
    for (int i = 1; i < NCLS; i++) m = fmaxf(m, p[i]);
    g_scores[r] = m;
}

// ---------------------------------------------------------------------------
// K2: exact jax.lax.top_k via rank counting.
// rank(r) = #{j : s_j > s_r} + #{j < r : s_j == s_r}  (total order, ties by index)
// One block per row; 256-thread partial counts + tree reduction.
// ---------------------------------------------------------------------------
__global__ void k_rank() {
    int r = blockIdx.x;
    float sr = g_scores[r];
    int cnt = 0;
    for (int j = threadIdx.x; j < NDET; j += blockDim.x) {
        float sj = g_scores[j];
        if (sj > sr || (sj == sr && j < r)) cnt++;
    }
    __shared__ int sh[256];
    sh[threadIdx.x] = cnt;
    __syncthreads();
    for (int s = 128; s > 0; s >>= 1) {
        if (threadIdx.x < s) sh[threadIdx.x] += sh[threadIdx.x + s];
        __syncthreads();
    }
    if (threadIdx.x == 0) {
        int rank = sh[0];
        if (rank < TOPK) g_sel[rank] = r;
    }
}

// ---------------------------------------------------------------------------
// K3: gather selected boxes (rank order) and compute FPN level
// ---------------------------------------------------------------------------
__global__ void k_level(const float* __restrict__ det) {
    int r = blockIdx.x * blockDim.x + threadIdx.x;
    if (r >= TOPK) return;
    int row = g_sel[r];
    const float* p = det + row * DETSTRIDE;
    float x1 = p[0], y1 = p[1], x2 = p[2], y2 = p[3];
    float w = x2 - x1;
    float h = y2 - y1;
    float size = sqrtf(w * h);
    float lv = floorf(1.0f + log2f(size / 224.0f + 1e-7f));
    lv = fminf(fmaxf(lv, 0.0f), 4.0f);
    g_rank_boxes[r][0] = x1;
    g_rank_boxes[r][1] = y1;
    g_rank_boxes[r][2] = x2;
    g_rank_boxes[r][3] = y2;
    g_rank_level[r] = (int)lv;
}

// ---------------------------------------------------------------------------
// K4: stable ascending sort by level via key counting.
// key = level*1024 + rank  (all keys distinct -> permutation)
// ---------------------------------------------------------------------------
__global__ void k_sort() {
    __shared__ int key[TOPK];
    for (int i = threadIdx.x; i < TOPK; i += blockDim.x)
        key[i] = g_rank_level[i] * 1024 + i;
    __syncthreads();
    int r = blockIdx.x * blockDim.x + threadIdx.x;
    if (r >= TOPK) return;
    int kr = key[r];
    int pos = 0;
#pragma unroll 8
    for (int j = 0; j < TOPK; j++) pos += (key[j] < kr) ? 1 : 0;
    g_boxes[pos][0] = g_rank_boxes[r][0];
    g_boxes[pos][1] = g_rank_boxes[r][1];
    g_boxes[pos][2] = g_rank_boxes[r][2];
    g_boxes[pos][3] = g_rank_boxes[r][3];
    g_level[pos] = g_rank_level[r];
}

// ---------------------------------------------------------------------------
// K5: crop_and_resize. One block = (box, output row). thread = channel.
// Replicates TF/jax semantics: normalized coords -> rescale, floor/clip/cast,
// bilinear blend, zero where sample falls outside [0, S-1].
// ---------------------------------------------------------------------------
__global__ void __launch_bounds__(CH) k_main(
    const float* __restrict__ p0, const float* __restrict__ p1,
    const float* __restrict__ p2, const float* __restrict__ p3,
    const float* __restrict__ p4, float* __restrict__ out)
{
    int b = blockIdx.y;
    int yi = blockIdx.x;
    int c = threadIdx.x;

    float x1 = g_boxes[b][0];
    float y1 = g_boxes[b][1];
    float x2 = g_boxes[b][2];
    float y2 = g_boxes[b][3];
    int lev = g_level[b];

    const float* feat;
    int S;
    switch (lev) {
        case 0:  feat = p0; S = 256; break;
        case 1:  feat = p1; S = 128; break;
        case 2:  feat = p2; S = 64;  break;
        case 3:  feat = p3; S = 32;  break;
        default: feat = p4; S = 16;  break;
    }
    float hf = (float)(S - 1);   // H == W for all levels

    // reference normalizes by (H-1)/(W-1) then rescales by the same factor
    float ny1 = y1 / hf, nx1 = x1 / hf;
    float ny2 = y2 / hf, nx2 = x2 / hf;

    float ty = (float)yi / 13.0f;
    float ys = (ny1 + (ny2 - ny1) * ty) * hf;
    bool vy = (ys >= 0.0f) && (ys <= hf);
    float y0f = floorf(ys);
    float ly = ys - y0f;
    int y0i = (int)fminf(fmaxf(y0f, 0.0f), hf);
    int y1i = (int)fminf(fmaxf(y0f + 1.0f, 0.0f), hf);

    const float* row0 = feat + (size_t)y0i * S * CH;
    const float* row1 = feat + (size_t)y1i * S * CH;
    float* orow = out + (((size_t)b * CROP + yi) * CROP) * CH + c;

#pragma unroll
    for (int xi = 0; xi < CROP; xi++) {
        float tx = (float)xi / 13.0f;
        float xs = (nx1 + (nx2 - nx1) * tx) * hf;
        bool vx = (xs >= 0.0f) && (xs <= hf);
        float x0f = floorf(xs);
        float lx = xs - x0f;
        int x0i = (int)fminf(fmaxf(x0f, 0.0f), hf);
        int x1i = (int)fminf(fmaxf(x0f + 1.0f, 0.0f), hf);

        float f00 = __ldg(row0 + x0i * CH + c);
        float f01 = __ldg(row0 + x1i * CH + c);
        float f10 = __ldg(row1 + x0i * CH + c);
        float f11 = __ldg(row1 + x1i * CH + c);

        float top = f00 + (f01 - f00) * lx;
        float bot = f10 + (f11 - f10) * lx;
        float v   = top + (bot - top) * ly;

        orow[(size_t)xi * CH] = (vy && vx) ? v : 0.0f;
    }
}

// ---------------------------------------------------------------------------
extern "C" void kernel_launch(void* const* d_in, const int* in_sizes, int n_in,
                              void* d_out, int out_size) {
    const float* det = (const float*)d_in[0];
    const float* p0  = (const float*)d_in[1];
    const float* p1  = (const float*)d_in[2];
    const float* p2  = (const float*)d_in[3];
    const float* p3  = (const float*)d_in[4];
    const float* p4  = (const float*)d_in[5];
    float* out = (float*)d_out;

    k_scores<<<(NDET + 255) / 256, 256>>>(det);
    k_rank<<<NDET, 256>>>();
    k_level<<<(TOPK + 255) / 256, 256>>>(det);
    k_sort<<<(TOPK + 255) / 256, 256>>>();

    dim3 grid(CROP, TOPK);
    k_main<<<grid, CH>>>(p0, p1, p2, p3, p4, out);
}

// round 2
// speedup vs baseline: 1.1599x; 1.1599x over previous
#include <cuda_runtime.h>

#define NDET      5000
#define TOPK      1000
#define NCLS      80
#define DETSTRIDE 84
#define CH        256
#define CROP      14

// Scratch (no allocations allowed in kernel_launch)
__device__ float g_scores[NDET];
__device__ int   g_sel[TOPK];            // rank -> original detection row
__device__ float4 g_boxes[TOPK];         // boxes after stable level sort
__device__ int    g_level[TOPK];

// ---------------------------------------------------------------------------
// K1: per-row max over 80 class scores
// ---------------------------------------------------------------------------
__global__ void k_scores(const float* __restrict__ det) {
    int r = blockIdx.x * blockDim.x + threadIdx.x;
    if (r >= NDET) return;
    const float* p = det + r * DETSTRIDE + 4;
    float m = p[0];
#pragma unroll 8
    for (int i = 1; i < NCLS; i++) m = fmaxf(m, p[i]);
    g_scores[r] = m;
}

// ---------------------------------------------------------------------------
// K2: exact jax.lax.top_k via rank counting. 8 rows per block, scores staged
// in shared once per block.
// rank(r) = #{j : s_j > s_r} + #{j < r : s_j == s_r}
// ---------------------------------------------------------------------------
#define RPB 8
__global__ void __launch_bounds__(256) k_rank() {
    __shared__ float s[NDET];
    __shared__ int blockcnt[RPB];
    int tid = threadIdx.x;
    for (int j = tid; j < NDET; j += 256) s[j] = g_scores[j];
    if (tid < RPB) blockcnt[tid] = 0;
    __syncthreads();

    int base = blockIdx.x * RPB;
    float sr[RPB];
#pragma unroll
    for (int k = 0; k < RPB; k++) sr[k] = s[base + k];

    int cnt[RPB];
#pragma unroll
    for (int k = 0; k < RPB; k++) cnt[k] = 0;

    for (int j = tid; j < NDET; j += 256) {
        float sj = s[j];
#pragma unroll
        for (int k = 0; k < RPB; k++)
            cnt[k] += (sj > sr[k] || (sj == sr[k] && j < base + k)) ? 1 : 0;
    }
    // warp reduce each counter, then atomic into shared
#pragma unroll
    for (int k = 0; k < RPB; k++) {
#pragma unroll
        for (int off = 16; off > 0; off >>= 1)
            cnt[k] += __shfl_down_sync(0xffffffffu, cnt[k], off);
    }
    if ((tid & 31) == 0) {
#pragma unroll
        for (int k = 0; k < RPB; k++) atomicAdd(&blockcnt[k], cnt[k]);
    }
    __syncthreads();
    if (tid < RPB) {
        int rank = blockcnt[tid];
        if (rank < TOPK) g_sel[rank] = base + tid;
    }
}

// ---------------------------------------------------------------------------
// K3: fused level computation + stable counting sort by level.
// Single block of 1024 threads. Pack 5-level one-hot into uint64 (10 bits per
// level; counts <= 1000 fit), block-wide inclusive scan via warp shuffles.
// ---------------------------------------------------------------------------
__global__ void __launch_bounds__(1024) k_level_sort(const float* __restrict__ det) {
    int r = threadIdx.x;
    float x1 = 0, y1 = 0, x2 = 0, y2 = 0;
    int lev = 0;
    unsigned long long onehot = 0ULL;
    if (r < TOPK) {
        const float* p = det + (size_t)g_sel[r] * DETSTRIDE;
        x1 = p[0]; y1 = p[1]; x2 = p[2]; y2 = p[3];
        float size = sqrtf((x2 - x1) * (y2 - y1));
        float lv = floorf(1.0f + log2f(size / 224.0f + 1e-7f));
        lv = fminf(fmaxf(lv, 0.0f), 4.0f);
        lev = (int)lv;
        onehot = 1ULL << (10 * lev);
    }
    // inclusive warp scan
    unsigned long long v = onehot;
    int lane = r & 31;
#pragma unroll
    for (int off = 1; off < 32; off <<= 1) {
        unsigned long long n = __shfl_up_sync(0xffffffffu, v, off);
        if (lane >= off) v += n;
    }
    __shared__ unsigned long long warpsum[32];
    int wid = r >> 5;
    if (lane == 31) warpsum[wid] = v;
    __syncthreads();
    if (r < 32) {
        unsigned long long w = warpsum[r];
#pragma unroll
        for (int off = 1; off < 32; off <<= 1) {
            unsigned long long n = __shfl_up_sync(0xffffffffu, w, off);
            if (r >= off) w += n;
        }
        warpsum[r] = w;
    }
    __syncthreads();
    unsigned long long incl = v + (wid > 0 ? warpsum[wid - 1] : 0ULL);
    unsigned long long total = warpsum[31];
    unsigned long long excl = incl - onehot;
    if (r < TOPK) {
        int before = 0;
#pragma unroll
        for (int l = 0; l < 4; l++)
            if (l < lev) before += (int)((total >> (10 * l)) & 1023ULL);
        int pos = before + (int)((excl >> (10 * lev)) & 1023ULL);
        g_boxes[pos] = make_float4(x1, y1, x2, y2);
        g_level[pos] = lev;
    }
}

// ---------------------------------------------------------------------------
// K4: crop_and_resize. One block per box, 256 threads =
// 64 float4-channel-groups x 4 row-groups. All loads/stores 16B vectorized.
// ---------------------------------------------------------------------------
__global__ void __launch_bounds__(256) k_main(
    const float* __restrict__ p0, const float* __restrict__ p1,
    const float* __restrict__ p2, const float* __restrict__ p3,
    const float* __restrict__ p4, float* __restrict__ out)
{
    int b  = blockIdx.x;
    int cg = threadIdx.x & 63;   // channel group (4 floats)
    int rg = threadIdx.x >> 6;   // row group (0..3)

    float4 box = g_boxes[b];
    int lev = g_level[b];

    const float* feat;
    int S;
    switch (lev) {
        case 0:  feat = p0; S = 256; break;
        case 1:  feat = p1; S = 128; break;
        case 2:  feat = p2; S = 64;  break;
        case 3:  feat = p3; S = 32;  break;
        default: feat = p4; S = 16;  break;
    }
    float hf = (float)(S - 1);   // H == W for all levels

    // reference normalizes then rescales by the same factor
    float ny1 = box.y / hf, nx1 = box.x / hf;
    float ny2 = box.w / hf, nx2 = box.z / hf;

    for (int yi = rg; yi < CROP; yi += 4) {
        float ty = (float)yi / 13.0f;
        float ys = (ny1 + (ny2 - ny1) * ty) * hf;
        bool vy = (ys >= 0.0f) && (ys <= hf);
        float y0f = floorf(ys);
        float ly = ys - y0f;
        int y0i = (int)fminf(fmaxf(y0f, 0.0f), hf);
        int y1i = (int)fminf(fmaxf(y0f + 1.0f, 0.0f), hf);

        const float4* row0 = (const float4*)(feat + (size_t)y0i * S * CH);
        const float4* row1 = (const float4*)(feat + (size_t)y1i * S * CH);
        float4* orow = (float4*)(out + (((size_t)b * CROP + yi) * CROP) * CH) + cg;

#pragma unroll
        for (int xi = 0; xi < CROP; xi++) {
            float tx = (float)xi / 13.0f;
            float xs = (nx1 + (nx2 - nx1) * tx) * hf;
            bool vx = (xs >= 0.0f) && (xs <= hf);
            float x0f = floorf(xs);
            float lx = xs - x0f;
            int x0i = (int)fminf(fmaxf(x0f, 0.0f), hf);
            int x1i = (int)fminf(fmaxf(x0f + 1.0f, 0.0f), hf);

            float4 f00 = __ldg(row0 + x0i * 64 + cg);
            float4 f01 = __ldg(row0 + x1i * 64 + cg);
            float4 f10 = __ldg(row1 + x0i * 64 + cg);
            float4 f11 = __ldg(row1 + x1i * 64 + cg);

            float4 v;
            {
                float t0 = f00.x + (f01.x - f00.x) * lx;
                float b0 = f10.x + (f11.x - f10.x) * lx;
                v.x = t0 + (b0 - t0) * ly;
                float t1 = f00.y + (f01.y - f00.y) * lx;
                float b1 = f10.y + (f11.y - f10.y) * lx;
                v.y = t1 + (b1 - t1) * ly;
                float t2 = f00.z + (f01.z - f00.z) * lx;
                float b2 = f10.z + (f11.z - f10.z) * lx;
                v.z = t2 + (b2 - t2) * ly;
                float t3 = f00.w + (f01.w - f00.w) * lx;
                float b3 = f10.w + (f11.w - f10.w) * lx;
                v.w = t3 + (b3 - t3) * ly;
            }
            if (!(vy && vx)) v = make_float4(0.f, 0.f, 0.f, 0.f);
            orow[(size_t)xi * 64] = v;
        }
    }
}

// ---------------------------------------------------------------------------
extern "C" void kernel_launch(void* const* d_in, const int* in_sizes, int n_in,
                              void* d_out, int out_size) {
    const float* det = (const float*)d_in[0];
    const float* p0  = (const float*)d_in[1];
    const float* p1  = (const float*)d_in[2];
    const float* p2  = (const float*)d_in[3];
    const float* p3  = (const float*)d_in[4];
    const float* p4  = (const float*)d_in[5];
    float* out = (float*)d_out;

    k_scores<<<(NDET + 255) / 256, 256>>>(det);
    k_rank<<<NDET / RPB, 256>>>();
    k_level_sort<<<1, 1024>>>(det);
    k_main<<<TOPK, 256>>>(p0, p1, p2, p3, p4, out);
}

// round 3
// speedup vs baseline: 1.4962x; 1.2899x over previous
#include <cuda_runtime.h>

#define NDET      5000
#define TOPK      1000
#define NCLS      80
#define DETSTRIDE 84
#define CH        256
#define CROP      14

// Scratch (no allocations allowed in kernel_launch)
__device__ float g_scores[NDET];
__device__ int   g_sel[TOPK];            // rank -> original detection row
__device__ float4 g_boxes[TOPK];         // boxes after stable level sort
__device__ int    g_level[TOPK];

// ---------------------------------------------------------------------------
// K1: per-row max over 80 class scores
// ---------------------------------------------------------------------------
__global__ void k_scores(const float* __restrict__ det) {
    int r = blockIdx.x * blockDim.x + threadIdx.x;
    if (r >= NDET) return;
    const float* p = det + r * DETSTRIDE + 4;
    float m = p[0];
#pragma unroll 8
    for (int i = 1; i < NCLS; i++) m = fmaxf(m, p[i]);
    g_scores[r] = m;
}

// ---------------------------------------------------------------------------
// K2: exact jax.lax.top_k via rank counting. 8 rows per block, scores staged
// in shared once per block.
// ---------------------------------------------------------------------------
#define RPB 8
__global__ void __launch_bounds__(256) k_rank() {
    __shared__ float s[NDET];
    __shared__ int blockcnt[RPB];
    int tid = threadIdx.x;
    for (int j = tid; j < NDET; j += 256) s[j] = g_scores[j];
    if (tid < RPB) blockcnt[tid] = 0;
    __syncthreads();

    int base = blockIdx.x * RPB;
    float sr[RPB];
#pragma unroll
    for (int k = 0; k < RPB; k++) sr[k] = s[base + k];

    int cnt[RPB];
#pragma unroll
    for (int k = 0; k < RPB; k++) cnt[k] = 0;

    for (int j = tid; j < NDET; j += 256) {
        float sj = s[j];
#pragma unroll
        for (int k = 0; k < RPB; k++)
            cnt[k] += (sj > sr[k] || (sj == sr[k] && j < base + k)) ? 1 : 0;
    }
#pragma unroll
    for (int k = 0; k < RPB; k++) {
#pragma unroll
        for (int off = 16; off > 0; off >>= 1)
            cnt[k] += __shfl_down_sync(0xffffffffu, cnt[k], off);
    }
    if ((tid & 31) == 0) {
#pragma unroll
        for (int k = 0; k < RPB; k++) atomicAdd(&blockcnt[k], cnt[k]);
    }
    __syncthreads();
    if (tid < RPB) {
        int rank = blockcnt[tid];
        if (rank < TOPK) g_sel[rank] = base + tid;
    }
}

// ---------------------------------------------------------------------------
// K3: fused level computation + stable counting sort by level (single block).
// ---------------------------------------------------------------------------
__global__ void __launch_bounds__(1024) k_level_sort(const float* __restrict__ det) {
    int r = threadIdx.x;
    float x1 = 0, y1 = 0, x2 = 0, y2 = 0;
    int lev = 0;
    unsigned long long onehot = 0ULL;
    if (r < TOPK) {
        const float* p = det + (size_t)g_sel[r] * DETSTRIDE;
        x1 = p[0]; y1 = p[1]; x2 = p[2]; y2 = p[3];
        float size = sqrtf((x2 - x1) * (y2 - y1));
        float lv = floorf(1.0f + log2f(size / 224.0f + 1e-7f));
        lv = fminf(fmaxf(lv, 0.0f), 4.0f);
        lev = (int)lv;
        onehot = 1ULL << (10 * lev);
    }
    unsigned long long v = onehot;
    int lane = r & 31;
#pragma unroll
    for (int off = 1; off < 32; off <<= 1) {
        unsigned long long n = __shfl_up_sync(0xffffffffu, v, off);
        if (lane >= off) v += n;
    }
    __shared__ unsigned long long warpsum[32];
    int wid = r >> 5;
    if (lane == 31) warpsum[wid] = v;
    __syncthreads();
    if (r < 32) {
        unsigned long long w = warpsum[r];
#pragma unroll
        for (int off = 1; off < 32; off <<= 1) {
            unsigned long long n = __shfl_up_sync(0xffffffffu, w, off);
            if (r >= off) w += n;
        }
        warpsum[r] = w;
    }
    __syncthreads();
    unsigned long long incl = v + (wid > 0 ? warpsum[wid - 1] : 0ULL);
    unsigned long long total = warpsum[31];
    unsigned long long excl = incl - onehot;
    if (r < TOPK) {
        int before = 0;
#pragma unroll
        for (int l = 0; l < 4; l++)
            if (l < lev) before += (int)((total >> (10 * l)) & 1023ULL);
        int pos = before + (int)((excl >> (10 * lev)) & 1023ULL);
        g_boxes[pos] = make_float4(x1, y1, x2, y2);
        g_level[pos] = lev;
    }
}

// ---------------------------------------------------------------------------
// K4: crop_and_resize. One block per box. Coordinate math hoisted to shared
// (28 threads compute 14 x-samples + 14 y-samples). Main loop is pure
// LDG.128 x4 + FFMA + STG.128 with smem-broadcast coefficients.
// ---------------------------------------------------------------------------
__global__ void __launch_bounds__(256, 3) k_main(
    const float* __restrict__ p0, const float* __restrict__ p1,
    const float* __restrict__ p2, const float* __restrict__ p3,
    const float* __restrict__ p4, float* __restrict__ out)
{
    __shared__ float s_lx[CROP], s_ly[CROP];
    __shared__ int   s_x0[CROP], s_x1[CROP];   // float4 offsets within a row
    __shared__ int   s_r0[CROP], s_r1[CROP];   // float4 offsets of rows
    __shared__ int   s_vx[CROP], s_vy[CROP];

    int b = blockIdx.x;
    float4 box = g_boxes[b];
    int lev = g_level[b];

    const float* feat;
    int S;
    switch (lev) {
        case 0:  feat = p0; S = 256; break;
        case 1:  feat = p1; S = 128; break;
        case 2:  feat = p2; S = 64;  break;
        case 3:  feat = p3; S = 32;  break;
        default: feat = p4; S = 16;  break;
    }
    float hf = (float)(S - 1);

    if (threadIdx.x < 2 * CROP) {
        int i = threadIdx.x;
        bool isy = i >= CROP;
        int k = isy ? i - CROP : i;
        float a1 = isy ? box.y : box.x;
        float a2 = isy ? box.w : box.z;
        // reference normalizes then rescales by the same (S-1) factor
        float n1 = a1 / hf, n2 = a2 / hf;
        float t = (float)k / 13.0f;
        float s = (n1 + (n2 - n1) * t) * hf;
        int valid = (s >= 0.0f && s <= hf) ? 1 : 0;
        float f0 = floorf(s);
        float l = s - f0;
        int i0 = (int)fminf(fmaxf(f0, 0.0f), hf);
        int i1 = (int)fminf(fmaxf(f0 + 1.0f, 0.0f), hf);
        if (isy) {
            s_ly[k] = l; s_vy[k] = valid;
            s_r0[k] = i0 * S * (CH / 4);
            s_r1[k] = i1 * S * (CH / 4);
        } else {
            s_lx[k] = l; s_vx[k] = valid;
            s_x0[k] = i0 * (CH / 4);
            s_x1[k] = i1 * (CH / 4);
        }
    }
    __syncthreads();

    int cg = threadIdx.x & 63;   // channel group (float4)
    int rg = threadIdx.x >> 6;   // row group (0..3)
    const float4* fp = (const float4*)feat;

    for (int yi = rg; yi < CROP; yi += 4) {
        int r0 = s_r0[yi] + cg;
        int r1 = s_r1[yi] + cg;
        float ly = s_ly[yi];
        int vy = s_vy[yi];
        float4* orow = (float4*)(out + (((size_t)b * CROP + yi) * CROP) * CH) + cg;

#pragma unroll
        for (int xi = 0; xi < CROP; xi++) {
            int x0 = s_x0[xi];
            int x1 = s_x1[xi];
            float lx = s_lx[xi];
            float m = (vy & s_vx[xi]) ? 1.0f : 0.0f;

            float4 f00 = __ldg(fp + r0 + x0);
            float4 f01 = __ldg(fp + r0 + x1);
            float4 f10 = __ldg(fp + r1 + x0);
            float4 f11 = __ldg(fp + r1 + x1);

            float4 v;
            float t0 = f00.x + (f01.x - f00.x) * lx;
            float b0 = f10.x + (f11.x - f10.x) * lx;
            v.x = (t0 + (b0 - t0) * ly) * m;
            float t1 = f00.y + (f01.y - f00.y) * lx;
            float b1 = f10.y + (f11.y - f10.y) * lx;
            v.y = (t1 + (b1 - t1) * ly) * m;
            float t2 = f00.z + (f01.z - f00.z) * lx;
            float b2 = f10.z + (f11.z - f10.z) * lx;
            v.z = (t2 + (b2 - t2) * ly) * m;
            float t3 = f00.w + (f01.w - f00.w) * lx;
            float b3 = f10.w + (f11.w - f10.w) * lx;
            v.w = (t3 + (b3 - t3) * ly) * m;

            orow[(size_t)xi * 64] = v;
        }
    }
}

// ---------------------------------------------------------------------------
extern "C" void kernel_launch(void* const* d_in, const int* in_sizes, int n_in,
                              void* d_out, int out_size) {
    const float* det = (const float*)d_in[0];
    const float* p0  = (const float*)d_in[1];
    const float* p1  = (const float*)d_in[2];
    const float* p2  = (const float*)d_in[3];
    const float* p3  = (const float*)d_in[4];
    const float* p4  = (const float*)d_in[5];
    float* out = (float*)d_out;

    k_scores<<<(NDET + 255) / 256, 256>>>(det);
    k_rank<<<NDET / RPB, 256>>>();
    k_level_sort<<<1, 1024>>>(det);
    k_main<<<TOPK, 256>>>(p0, p1, p2, p3, p4, out);
}

// round 5
// speedup vs baseline: 1.6194x; 1.0824x over previous
#include <cuda_runtime.h>

#define NDET      5000
#define TOPK      1000
#define NCLS      80
#define DETSTRIDE 84
#define CH        256
#define CROP      14

// Scratch (no allocations allowed in kernel_launch)
__device__ float g_scores[NDET];
__device__ int   g_sel[TOPK];            // rank -> original detection row
__device__ float4 g_boxes[TOPK];         // boxes after stable level sort
__device__ int    g_level[TOPK];

// ---------------------------------------------------------------------------
// K1: per-row max over 80 class scores
// ---------------------------------------------------------------------------
__global__ void k_scores(const float* __restrict__ det) {
    int r = blockIdx.x * blockDim.x + threadIdx.x;
    if (r >= NDET) return;
    const float* p = det + r * DETSTRIDE + 4;
    float m = p[0];
#pragma unroll 8
    for (int i = 1; i < NCLS; i++) m = fmaxf(m, p[i]);
    g_scores[r] = m;
}

// ---------------------------------------------------------------------------
// K2: exact jax.lax.top_k via rank counting. 8 rows per block (5000/8 = 625
// blocks, exact), scores staged in shared once per block.
// ---------------------------------------------------------------------------
#define RPB 8
__global__ void __launch_bounds__(256) k_rank() {
    __shared__ float s[NDET];
    __shared__ int blockcnt[RPB];
    int tid = threadIdx.x;
    for (int j = tid; j < NDET; j += 256) s[j] = g_scores[j];
    if (tid < RPB) blockcnt[tid] = 0;
    __syncthreads();

    int base = blockIdx.x * RPB;
    float sr[RPB];
#pragma unroll
    for (int k = 0; k < RPB; k++) sr[k] = s[base + k];

    int cnt[RPB];
#pragma unroll
    for (int k = 0; k < RPB; k++) cnt[k] = 0;

    for (int j = tid; j < NDET; j += 256) {
        float sj = s[j];
#pragma unroll
        for (int k = 0; k < RPB; k++)
            cnt[k] += (sj > sr[k] || (sj == sr[k] && j < base + k)) ? 1 : 0;
    }
#pragma unroll
    for (int k = 0; k < RPB; k++) {
#pragma unroll
        for (int off = 16; off > 0; off >>= 1)
            cnt[k] += __shfl_down_sync(0xffffffffu, cnt[k], off);
    }
    if ((tid & 31) == 0) {
#pragma unroll
        for (int k = 0; k < RPB; k++) atomicAdd(&blockcnt[k], cnt[k]);
    }
    __syncthreads();
    if (tid < RPB) {
        int rank = blockcnt[tid];
        if (rank < TOPK) g_sel[rank] = base + tid;
    }
}

// ---------------------------------------------------------------------------
// K3: fused level computation + stable counting sort by level (single block).
// ---------------------------------------------------------------------------
__global__ void __launch_bounds__(1024) k_level_sort(const float* __restrict__ det) {
    int r = threadIdx.x;
    float x1 = 0, y1 = 0, x2 = 0, y2 = 0;
    int lev = 0;
    unsigned long long onehot = 0ULL;
    if (r < TOPK) {
        const float* p = det + (size_t)g_sel[r] * DETSTRIDE;
        x1 = p[0]; y1 = p[1]; x2 = p[2]; y2 = p[3];
        float size = sqrtf((x2 - x1) * (y2 - y1));
        float lv = floorf(1.0f + log2f(size / 224.0f + 1e-7f));
        lv = fminf(fmaxf(lv, 0.0f), 4.0f);
        lev = (int)lv;
        onehot = 1ULL << (10 * lev);
    }
    unsigned long long v = onehot;
    int lane = r & 31;
#pragma unroll
    for (int off = 1; off < 32; off <<= 1) {
        unsigned long long n = __shfl_up_sync(0xffffffffu, v, off);
        if (lane >= off) v += n;
    }
    __shared__ unsigned long long warpsum[32];
    int wid = r >> 5;
    if (lane == 31) warpsum[wid] = v;
    __syncthreads();
    if (r < 32) {
        unsigned long long w = warpsum[r];
#pragma unroll
        for (int off = 1; off < 32; off <<= 1) {
            unsigned long long n = __shfl_up_sync(0xffffffffu, w, off);
            if (r >= off) w += n;
        }
        warpsum[r] = w;
    }
    __syncthreads();
    unsigned long long incl = v + (wid > 0 ? warpsum[wid - 1] : 0ULL);
    unsigned long long total = warpsum[31];
    unsigned long long excl = incl - onehot;
    if (r < TOPK) {
        int before = 0;
#pragma unroll
        for (int l = 0; l < 4; l++)
            if (l < lev) before += (int)((total >> (10 * l)) & 1023ULL);
        int pos = before + (int)((excl >> (10 * lev)) & 1023ULL);
        g_boxes[pos] = make_float4(x1, y1, x2, y2);
        g_level[pos] = lev;
    }
}

// ---------------------------------------------------------------------------
// K4: crop_and_resize. One block per box, coordinate math hoisted to shared.
// 4 blocks/SM for latency hiding; streaming stores keep features in L2.
// ---------------------------------------------------------------------------
__global__ void __launch_bounds__(256, 4) k_main(
    const float* __restrict__ p0, const float* __restrict__ p1,
    const float* __restrict__ p2, const float* __restrict__ p3,
    const float* __restrict__ p4, float* __restrict__ out)
{
    __shared__ float s_lx[CROP], s_ly[CROP];
    __shared__ int   s_x0[CROP], s_x1[CROP];   // float4 offsets within a row
    __shared__ int   s_r0[CROP], s_r1[CROP];   // float4 offsets of rows
    __shared__ int   s_vx[CROP], s_vy[CROP];

    int b = blockIdx.x;
    float4 box = g_boxes[b];
    int lev = g_level[b];

    const float* feat;
    int S;
    switch (lev) {
        case 0:  feat = p0; S = 256; break;
        case 1:  feat = p1; S = 128; break;
        case 2:  feat = p2; S = 64;  break;
        case 3:  feat = p3; S = 32;  break;
        default: feat = p4; S = 16;  break;
    }
    float hf = (float)(S - 1);

    if (threadIdx.x < 2 * CROP) {
        int i = threadIdx.x;
        bool isy = i >= CROP;
        int k = isy ? i - CROP : i;
        float a1 = isy ? box.y : box.x;
        float a2 = isy ? box.w : box.z;
        // reference normalizes then rescales by the same (S-1) factor
        float n1 = a1 / hf, n2 = a2 / hf;
        float t = (float)k / 13.0f;
        float s = (n1 + (n2 - n1) * t) * hf;
        int valid = (s >= 0.0f && s <= hf) ? 1 : 0;
        float f0 = floorf(s);
        float l = s - f0;
        int i0 = (int)fminf(fmaxf(f0, 0.0f), hf);
        int i1 = (int)fminf(fmaxf(f0 + 1.0f, 0.0f), hf);
        if (isy) {
            s_ly[k] = l; s_vy[k] = valid;
            s_r0[k] = i0 * S * (CH / 4);
            s_r1[k] = i1 * S * (CH / 4);
        } else {
            s_lx[k] = l; s_vx[k] = valid;
            s_x0[k] = i0 * (CH / 4);
            s_x1[k] = i1 * (CH / 4);
        }
    }
    __syncthreads();

    int cg = threadIdx.x & 63;   // channel group (float4)
    int rg = threadIdx.x >> 6;   // row group (0..3)
    const float4* fp = (const float4*)feat;

    for (int yi = rg; yi < CROP; yi += 4) {
        int r0 = s_r0[yi] + cg;
        int r1 = s_r1[yi] + cg;
        float ly = s_ly[yi];
        int vy = s_vy[yi];
        float4* orow = (float4*)(out + (((size_t)b * CROP + yi) * CROP) * CH) + cg;

#pragma unroll
        for (int xi = 0; xi < CROP; xi++) {
            int x0 = s_x0[xi];
            int x1 = s_x1[xi];
            float lx = s_lx[xi];
            float m = (vy & s_vx[xi]) ? 1.0f : 0.0f;

            float4 f00 = __ldg(fp + r0 + x0);
            float4 f01 = __ldg(fp + r0 + x1);
            float4 f10 = __ldg(fp + r1 + x0);
            float4 f11 = __ldg(fp + r1 + x1);

            float4 v;
            float t0 = f00.x + (f01.x - f00.x) * lx;
            float b0 = f10.x + (f11.x - f10.x) * lx;
            v.x = (t0 + (b0 - t0) * ly) * m;
            float t1 = f00.y + (f01.y - f00.y) * lx;
            float b1 = f10.y + (f11.y - f10.y) * lx;
            v.y = (t1 + (b1 - t1) * ly) * m;
            float t2 = f00.z + (f01.z - f00.z) * lx;
            float b2 = f10.z + (f11.z - f10.z) * lx;
            v.z = (t2 + (b2 - t2) * ly) * m;
            float t3 = f00.w + (f01.w - f00.w) * lx;
            float b3 = f10.w + (f11.w - f10.w) * lx;
            v.w = (t3 + (b3 - t3) * ly) * m;

            __stcs(orow + (size_t)xi * 64, v);   // streaming: don't pollute L2
        }
    }
}

// ---------------------------------------------------------------------------
extern "C" void kernel_launch(void* const* d_in, const int* in_sizes, int n_in,
                              void* d_out, int out_size) {
    const float* det = (const float*)d_in[0];
    const float* p0  = (const float*)d_in[1];
    const float* p1  = (const float*)d_in[2];
    const float* p2  = (const float*)d_in[3];
    const float* p3  = (const float*)d_in[4];
    const float* p4  = (const float*)d_in[5];
    float* out = (float*)d_out;

    k_scores<<<(NDET + 255) / 256, 256>>>(det);
    k_rank<<<NDET / RPB, 256>>>();
    k_level_sort<<<1, 1024>>>(det);
    k_main<<<TOPK, 256>>>(p0, p1, p2, p3, p4, out);
}

// round 6
// speedup vs baseline: 1.7153x; 1.0592x over previous
#include <cuda_runtime.h>

#define NDET      5000
#define TOPK      1000
#define NCLS      80
#define DETSTRIDE 84
#define CH        256
#define CROP      14

// Scratch (no allocations allowed in kernel_launch)
__device__ float g_scores[NDET];
__device__ int   g_sel[TOPK];            // rank -> original detection row
__device__ float4 g_boxes[TOPK];         // boxes after stable level sort
__device__ int    g_level[TOPK];

// ---------------------------------------------------------------------------
// K1: per-row max over 80 class scores. Warp per row, coalesced reads.
// ---------------------------------------------------------------------------
__global__ void __launch_bounds__(256) k_scores(const float* __restrict__ det) {
    int warp = (blockIdx.x * blockDim.x + threadIdx.x) >> 5;
    int lane = threadIdx.x & 31;
    if (warp >= NDET) return;
    const float* p = det + (size_t)warp * DETSTRIDE + 4;
    float m = -3.402823466e+38f;
    for (int i = lane; i < NCLS; i += 32) m = fmaxf(m, p[i]);
#pragma unroll
    for (int off = 16; off > 0; off >>= 1)
        m = fmaxf(m, __shfl_xor_sync(0xffffffffu, m, off));
    if (lane == 0) g_scores[warp] = m;
}

// ---------------------------------------------------------------------------
// K2: exact jax.lax.top_k via rank counting. 8 rows per block (5000/8 = 625
// blocks, exact), scores staged in shared once per block.
// ---------------------------------------------------------------------------
#define RPB 8
__global__ void __launch_bounds__(256) k_rank() {
    __shared__ float s[NDET];
    __shared__ int blockcnt[RPB];
    int tid = threadIdx.x;
    for (int j = tid; j < NDET; j += 256) s[j] = g_scores[j];
    if (tid < RPB) blockcnt[tid] = 0;
    __syncthreads();

    int base = blockIdx.x * RPB;
    float sr[RPB];
#pragma unroll
    for (int k = 0; k < RPB; k++) sr[k] = s[base + k];

    int cnt[RPB];
#pragma unroll
    for (int k = 0; k < RPB; k++) cnt[k] = 0;

    for (int j = tid; j < NDET; j += 256) {
        float sj = s[j];
#pragma unroll
        for (int k = 0; k < RPB; k++)
            cnt[k] += (sj > sr[k] || (sj == sr[k] && j < base + k)) ? 1 : 0;
    }
#pragma unroll
    for (int k = 0; k < RPB; k++) {
#pragma unroll
        for (int off = 16; off > 0; off >>= 1)
            cnt[k] += __shfl_down_sync(0xffffffffu, cnt[k], off);
    }
    if ((tid & 31) == 0) {
#pragma unroll
        for (int k = 0; k < RPB; k++) atomicAdd(&blockcnt[k], cnt[k]);
    }
    __syncthreads();
    if (tid < RPB) {
        int rank = blockcnt[tid];
        if (rank < TOPK) g_sel[rank] = base + tid;
    }
}

// ---------------------------------------------------------------------------
// K3: fused level computation + stable counting sort by level (single block).
// ---------------------------------------------------------------------------
__global__ void __launch_bounds__(1024) k_level_sort(const float* __restrict__ det) {
    int r = threadIdx.x;
    float x1 = 0, y1 = 0, x2 = 0, y2 = 0;
    int lev = 0;
    unsigned long long onehot = 0ULL;
    if (r < TOPK) {
        const float* p = det + (size_t)g_sel[r] * DETSTRIDE;
        x1 = p[0]; y1 = p[1]; x2 = p[2]; y2 = p[3];
        float size = sqrtf((x2 - x1) * (y2 - y1));
        float lv = floorf(1.0f + log2f(size / 224.0f + 1e-7f));
        lv = fminf(fmaxf(lv, 0.0f), 4.0f);
        lev = (int)lv;
        onehot = 1ULL << (10 * lev);
    }
    unsigned long long v = onehot;
    int lane = r & 31;
#pragma unroll
    for (int off = 1; off < 32; off <<= 1) {
        unsigned long long n = __shfl_up_sync(0xffffffffu, v, off);
        if (lane >= off) v += n;
    }
    __shared__ unsigned long long warpsum[32];
    int wid = r >> 5;
    if (lane == 31) warpsum[wid] = v;
    __syncthreads();
    if (r < 32) {
        unsigned long long w = warpsum[r];
#pragma unroll
        for (int off = 1; off < 32; off <<= 1) {
            unsigned long long n = __shfl_up_sync(0xffffffffu, w, off);
            if (r >= off) w += n;
        }
        warpsum[r] = w;
    }
    __syncthreads();
    unsigned long long incl = v + (wid > 0 ? warpsum[wid - 1] : 0ULL);
    unsigned long long total = warpsum[31];
    unsigned long long excl = incl - onehot;
    if (r < TOPK) {
        int before = 0;
#pragma unroll
        for (int l = 0; l < 4; l++)
            if (l < lev) before += (int)((total >> (10 * l)) & 1023ULL);
        int pos = before + (int)((excl >> (10 * lev)) & 1023ULL);
        g_boxes[pos] = make_float4(x1, y1, x2, y2);
        g_level[pos] = lev;
    }
}

// ---------------------------------------------------------------------------
// K4: crop_and_resize. One block per box, coordinate math hoisted to shared.
// KEY: samples outside [0, S-1] are zeros -> store zero and SKIP all 4 tap
// loads (warp-uniform branch; most points are invalid since boxes live in
// 0..1024 pixel space but S <= 256).
// ---------------------------------------------------------------------------
__global__ void __launch_bounds__(256, 4) k_main(
    const float* __restrict__ p0, const float* __restrict__ p1,
    const float* __restrict__ p2, const float* __restrict__ p3,
    const float* __restrict__ p4, float* __restrict__ out)
{
    __shared__ float s_lx[CROP], s_ly[CROP];
    __shared__ int   s_x0[CROP], s_x1[CROP];   // float4 offsets within a row
    __shared__ int   s_r0[CROP], s_r1[CROP];   // float4 offsets of rows
    __shared__ int   s_vx[CROP], s_vy[CROP];

    int b = blockIdx.x;
    float4 box = g_boxes[b];
    int lev = g_level[b];

    const float* feat;
    int S;
    switch (lev) {
        case 0:  feat = p0; S = 256; break;
        case 1:  feat = p1; S = 128; break;
        case 2:  feat = p2; S = 64;  break;
        case 3:  feat = p3; S = 32;  break;
        default: feat = p4; S = 16;  break;
    }
    float hf = (float)(S - 1);

    if (threadIdx.x < 2 * CROP) {
        int i = threadIdx.x;
        bool isy = i >= CROP;
        int k = isy ? i - CROP : i;
        float a1 = isy ? box.y : box.x;
        float a2 = isy ? box.w : box.z;
        // reference normalizes then rescales by the same (S-1) factor
        float n1 = a1 / hf, n2 = a2 / hf;
        float t = (float)k / 13.0f;
        float s = (n1 + (n2 - n1) * t) * hf;
        int valid = (s >= 0.0f && s <= hf) ? 1 : 0;
        float f0 = floorf(s);
        float l = s - f0;
        int i0 = (int)fminf(fmaxf(f0, 0.0f), hf);
        int i1 = (int)fminf(fmaxf(f0 + 1.0f, 0.0f), hf);
        if (isy) {
            s_ly[k] = l; s_vy[k] = valid;
            s_r0[k] = i0 * S * (CH / 4);
            s_r1[k] = i1 * S * (CH / 4);
        } else {
            s_lx[k] = l; s_vx[k] = valid;
            s_x0[k] = i0 * (CH / 4);
            s_x1[k] = i1 * (CH / 4);
        }
    }
    __syncthreads();

    int cg = threadIdx.x & 63;   // channel group (float4)
    int rg = threadIdx.x >> 6;   // row group (0..3)
    const float4* fp = (const float4*)feat;
    const float4 zero4 = make_float4(0.f, 0.f, 0.f, 0.f);

    for (int yi = rg; yi < CROP; yi += 4) {
        float4* orow = (float4*)(out + (((size_t)b * CROP + yi) * CROP) * CH) + cg;
        int vy = s_vy[yi];

        if (!vy) {
            // whole output row is zeros: no loads at all
#pragma unroll
            for (int xi = 0; xi < CROP; xi++)
                __stcs(orow + (size_t)xi * 64, zero4);
            continue;
        }

        int r0 = s_r0[yi] + cg;
        int r1 = s_r1[yi] + cg;
        float ly = s_ly[yi];

#pragma unroll
        for (int xi = 0; xi < CROP; xi++) {
            if (!s_vx[xi]) {             // warp-uniform: all 64 threads agree
                __stcs(orow + (size_t)xi * 64, zero4);
                continue;
            }
            int x0 = s_x0[xi];
            int x1 = s_x1[xi];
            float lx = s_lx[xi];

            float4 f00 = __ldg(fp + r0 + x0);
            float4 f01 = __ldg(fp + r0 + x1);
            float4 f10 = __ldg(fp + r1 + x0);
            float4 f11 = __ldg(fp + r1 + x1);

            float4 v;
            float t0 = f00.x + (f01.x - f00.x) * lx;
            float b0 = f10.x + (f11.x - f10.x) * lx;
            v.x = t0 + (b0 - t0) * ly;
            float t1 = f00.y + (f01.y - f00.y) * lx;
            float b1 = f10.y + (f11.y - f10.y) * lx;
            v.y = t1 + (b1 - t1) * ly;
            float t2 = f00.z + (f01.z - f00.z) * lx;
            float b2 = f10.z + (f11.z - f10.z) * lx;
            v.z = t2 + (b2 - t2) * ly;
            float t3 = f00.w + (f01.w - f00.w) * lx;
            float b3 = f10.w + (f11.w - f10.w) * lx;
            v.w = t3 + (b3 - t3) * ly;

            __stcs(orow + (size_t)xi * 64, v);
        }
    }
}

// ---------------------------------------------------------------------------
extern "C" void kernel_launch(void* const* d_in, const int* in_sizes, int n_in,
                              void* d_out, int out_size) {
    const float* det = (const float*)d_in[0];
    const float* p0  = (const float*)d_in[1];
    const float* p1  = (const float*)d_in[2];
    const float* p2  = (const float*)d_in[3];
    const float* p3  = (const float*)d_in[4];
    const float* p4  = (const float*)d_in[5];
    float* out = (float*)d_out;

    k_scores<<<(NDET * 32 + 255) / 256, 256>>>(det);
    k_rank<<<NDET / RPB, 256>>>();
    k_level_sort<<<1, 1024>>>(det);
    k_main<<<TOPK, 256>>>(p0, p1, p2, p3, p4, out);
}

// round 7
// speedup vs baseline: 1.8233x; 1.0630x over previous
#include <cuda_runtime.h>

#define NDET      5000
#define TOPK      1000
#define NCLS      80
#define DETSTRIDE 84
#define CH        256
#define CROP      14

// Scratch (no allocations allowed in kernel_launch)
__device__ float g_scores[NDET];
__device__ int   g_sel[TOPK];            // rank -> original detection row
__device__ float4 g_boxes[TOPK];         // boxes after stable level sort
__device__ int    g_level[TOPK];

// ---------------------------------------------------------------------------
// K1: per-row max over 80 class scores. Warp per row, coalesced reads.
// ---------------------------------------------------------------------------
__global__ void __launch_bounds__(256) k_scores(const float* __restrict__ det) {
    int warp = (blockIdx.x * blockDim.x + threadIdx.x) >> 5;
    int lane = threadIdx.x & 31;
    if (warp >= NDET) return;
    const float* p = det + (size_t)warp * DETSTRIDE + 4;
    float m = -3.402823466e+38f;
    for (int i = lane; i < NCLS; i += 32) m = fmaxf(m, p[i]);
#pragma unroll
    for (int off = 16; off > 0; off >>= 1)
        m = fmaxf(m, __shfl_xor_sync(0xffffffffu, m, off));
    if (lane == 0) g_scores[warp] = m;
}

// ---------------------------------------------------------------------------
// K2: exact jax.lax.top_k via rank counting. 8 rows per block (5000/8 = 625
// blocks, exact), scores staged in shared once per block.
// ---------------------------------------------------------------------------
#define RPB 8
__global__ void __launch_bounds__(256) k_rank() {
    __shared__ float s[NDET];
    __shared__ int blockcnt[RPB];
    int tid = threadIdx.x;
    for (int j = tid; j < NDET; j += 256) s[j] = g_scores[j];
    if (tid < RPB) blockcnt[tid] = 0;
    __syncthreads();

    int base = blockIdx.x * RPB;
    float sr[RPB];
#pragma unroll
    for (int k = 0; k < RPB; k++) sr[k] = s[base + k];

    int cnt[RPB];
#pragma unroll
    for (int k = 0; k < RPB; k++) cnt[k] = 0;

    for (int j = tid; j < NDET; j += 256) {
        float sj = s[j];
#pragma unroll
        for (int k = 0; k < RPB; k++)
            cnt[k] += (sj > sr[k] || (sj == sr[k] && j < base + k)) ? 1 : 0;
    }
#pragma unroll
    for (int k = 0; k < RPB; k++) {
#pragma unroll
        for (int off = 16; off > 0; off >>= 1)
            cnt[k] += __shfl_down_sync(0xffffffffu, cnt[k], off);
    }
    if ((tid & 31) == 0) {
#pragma unroll
        for (int k = 0; k < RPB; k++) atomicAdd(&blockcnt[k], cnt[k]);
    }
    __syncthreads();
    if (tid < RPB) {
        int rank = blockcnt[tid];
        if (rank < TOPK) g_sel[rank] = base + tid;
    }
}

// ---------------------------------------------------------------------------
// K3: fused level computation + stable counting sort by level (single block).
// ---------------------------------------------------------------------------
__global__ void __launch_bounds__(1024) k_level_sort(const float* __restrict__ det) {
    int r = threadIdx.x;
    float x1 = 0, y1 = 0, x2 = 0, y2 = 0;
    int lev = 0;
    unsigned long long onehot = 0ULL;
    if (r < TOPK) {
        const float* p = det + (size_t)g_sel[r] * DETSTRIDE;
        x1 = p[0]; y1 = p[1]; x2 = p[2]; y2 = p[3];
        float size = sqrtf((x2 - x1) * (y2 - y1));
        float lv = floorf(1.0f + log2f(size / 224.0f + 1e-7f));
        lv = fminf(fmaxf(lv, 0.0f), 4.0f);
        lev = (int)lv;
        onehot = 1ULL << (10 * lev);
    }
    unsigned long long v = onehot;
    int lane = r & 31;
#pragma unroll
    for (int off = 1; off < 32; off <<= 1) {
        unsigned long long n = __shfl_up_sync(0xffffffffu, v, off);
        if (lane >= off) v += n;
    }
    __shared__ unsigned long long warpsum[32];
    int wid = r >> 5;
    if (lane == 31) warpsum[wid] = v;
    __syncthreads();
    if (r < 32) {
        unsigned long long w = warpsum[r];
#pragma unroll
        for (int off = 1; off < 32; off <<= 1) {
            unsigned long long n = __shfl_up_sync(0xffffffffu, w, off);
            if (r >= off) w += n;
        }
        warpsum[r] = w;
    }
    __syncthreads();
    unsigned long long incl = v + (wid > 0 ? warpsum[wid - 1] : 0ULL);
    unsigned long long total = warpsum[31];
    unsigned long long excl = incl - onehot;
    if (r < TOPK) {
        int before = 0;
#pragma unroll
        for (int l = 0; l < 4; l++)
            if (l < lev) before += (int)((total >> (10 * l)) & 1023ULL);
        int pos = before + (int)((excl >> (10 * lev)) & 1023ULL);
        g_boxes[pos] = make_float4(x1, y1, x2, y2);
        g_level[pos] = lev;
    }
}

// ---------------------------------------------------------------------------
// K4: crop_and_resize. One block per box. Valid x-columns compacted into a
// shared list -> hot loop is branchless over valid points only, 2 points per
// iteration (8 independent LDG.128/thread) to keep MLP high. Invalid columns
// and rows get pure zero stores with no loads.
// ---------------------------------------------------------------------------
__global__ void __launch_bounds__(256, 4) k_main(
    const float* __restrict__ p0, const float* __restrict__ p1,
    const float* __restrict__ p2, const float* __restrict__ p3,
    const float* __restrict__ p4, float* __restrict__ out)
{
    __shared__ float s_lx[CROP], s_ly[CROP];
    __shared__ int   s_x0[CROP], s_x1[CROP];   // float4 offsets within a row
    __shared__ int   s_r0[CROP], s_r1[CROP];   // float4 offsets of rows
    __shared__ int   s_vx[CROP], s_vy[CROP];
    __shared__ int   s_xlist[CROP], s_xinv[CROP];
    __shared__ int   s_nx, s_ninv;

    int b = blockIdx.x;
    float4 box = g_boxes[b];
    int lev = g_level[b];

    const float* feat;
    int S;
    switch (lev) {
        case 0:  feat = p0; S = 256; break;
        case 1:  feat = p1; S = 128; break;
        case 2:  feat = p2; S = 64;  break;
        case 3:  feat = p3; S = 32;  break;
        default: feat = p4; S = 16;  break;
    }
    float hf = (float)(S - 1);

    if (threadIdx.x < 2 * CROP) {
        int i = threadIdx.x;
        bool isy = i >= CROP;
        int k = isy ? i - CROP : i;
        float a1 = isy ? box.y : box.x;
        float a2 = isy ? box.w : box.z;
        // reference normalizes then rescales by the same (S-1) factor
        float n1 = a1 / hf, n2 = a2 / hf;
        float t = (float)k / 13.0f;
        float s = (n1 + (n2 - n1) * t) * hf;
        int valid = (s >= 0.0f && s <= hf) ? 1 : 0;
        float f0 = floorf(s);
        float l = s - f0;
        int i0 = (int)fminf(fmaxf(f0, 0.0f), hf);
        int i1 = (int)fminf(fmaxf(f0 + 1.0f, 0.0f), hf);
        if (isy) {
            s_ly[k] = l; s_vy[k] = valid;
            s_r0[k] = i0 * S * (CH / 4);
            s_r1[k] = i1 * S * (CH / 4);
        } else {
            s_lx[k] = l; s_vx[k] = valid;
            s_x0[k] = i0 * (CH / 4);
            s_x1[k] = i1 * (CH / 4);
        }
    }
    __syncthreads();
    if (threadIdx.x == 0) {
        int n = 0, m = 0;
#pragma unroll
        for (int i = 0; i < CROP; i++) {
            if (s_vx[i]) s_xlist[n++] = i;
            else         s_xinv[m++]  = i;
        }
        s_nx = n; s_ninv = m;
    }
    __syncthreads();

    int cg = threadIdx.x & 63;   // channel group (float4)
    int rg = threadIdx.x >> 6;   // row group (0..3)
    const float4* fp = (const float4*)feat;
    const float4 zero4 = make_float4(0.f, 0.f, 0.f, 0.f);
    int nv = s_nx, ni = s_ninv;

    for (int yi = rg; yi < CROP; yi += 4) {
        float4* orow = (float4*)(out + (((size_t)b * CROP + yi) * CROP) * CH) + cg;

        if (!s_vy[yi]) {
#pragma unroll
            for (int xi = 0; xi < CROP; xi++)
                __stcs(orow + (size_t)xi * 64, zero4);
            continue;
        }

        // zero-fill invalid columns (no loads)
        for (int k = 0; k < ni; k++)
            __stcs(orow + (size_t)s_xinv[k] * 64, zero4);

        int r0 = s_r0[yi] + cg;
        int r1 = s_r1[yi] + cg;
        float ly = s_ly[yi];

        int j = 0;
        for (; j + 2 <= nv; j += 2) {
            int xa = s_xlist[j];
            int xb = s_xlist[j + 1];
            int a0 = s_x0[xa], a1 = s_x1[xa];
            int b0i = s_x0[xb], b1i = s_x1[xb];
            float lxa = s_lx[xa], lxb = s_lx[xb];

            float4 A00 = __ldg(fp + r0 + a0);
            float4 A01 = __ldg(fp + r0 + a1);
            float4 A10 = __ldg(fp + r1 + a0);
            float4 A11 = __ldg(fp + r1 + a1);
            float4 B00 = __ldg(fp + r0 + b0i);
            float4 B01 = __ldg(fp + r0 + b1i);
            float4 B10 = __ldg(fp + r1 + b0i);
            float4 B11 = __ldg(fp + r1 + b1i);

            float4 va, vb;
            {
                float t, bo;
                t = A00.x + (A01.x - A00.x) * lxa; bo = A10.x + (A11.x - A10.x) * lxa; va.x = t + (bo - t) * ly;
                t = A00.y + (A01.y - A00.y) * lxa; bo = A10.y + (A11.y - A10.y) * lxa; va.y = t + (bo - t) * ly;
                t = A00.z + (A01.z - A00.z) * lxa; bo = A10.z + (A11.z - A10.z) * lxa; va.z = t + (bo - t) * ly;
                t = A00.w + (A01.w - A00.w) * lxa; bo = A10.w + (A11.w - A10.w) * lxa; va.w = t + (bo - t) * ly;
                t = B00.x + (B01.x - B00.x) * lxb; bo = B10.x + (B11.x - B10.x) * lxb; vb.x = t + (bo - t) * ly;
                t = B00.y + (B01.y - B00.y) * lxb; bo = B10.y + (B11.y - B10.y) * lxb; vb.y = t + (bo - t) * ly;
                t = B00.z + (B01.z - B00.z) * lxb; bo = B10.z + (B11.z - B10.z) * lxb; vb.z = t + (bo - t) * ly;
                t = B00.w + (B01.w - B00.w) * lxb; bo = B10.w + (B11.w - B10.w) * lxb; vb.w = t + (bo - t) * ly;
            }
            __stcs(orow + (size_t)xa * 64, va);
            __stcs(orow + (size_t)xb * 64, vb);
        }
        if (j < nv) {
            int xa = s_xlist[j];
            int a0 = s_x0[xa], a1 = s_x1[xa];
            float lxa = s_lx[xa];
            float4 A00 = __ldg(fp + r0 + a0);
            float4 A01 = __ldg(fp + r0 + a1);
            float4 A10 = __ldg(fp + r1 + a0);
            float4 A11 = __ldg(fp + r1 + a1);
            float4 va;
            float t, bo;
            t = A00.x + (A01.x - A00.x) * lxa; bo = A10.x + (A11.x - A10.x) * lxa; va.x = t + (bo - t) * ly;
            t = A00.y + (A01.y - A00.y) * lxa; bo = A10.y + (A11.y - A10.y) * lxa; va.y = t + (bo - t) * ly;
            t = A00.z + (A01.z - A00.z) * lxa; bo = A10.z + (A11.z - A10.z) * lxa; va.z = t + (bo - t) * ly;
            t = A00.w + (A01.w - A00.w) * lxa; bo = A10.w + (A11.w - A10.w) * lxa; va.w = t + (bo - t) * ly;
            __stcs(orow + (size_t)xa * 64, va);
        }
    }
}

// ---------------------------------------------------------------------------
extern "C" void kernel_launch(void* const* d_in, const int* in_sizes, int n_in,
                              void* d_out, int out_size) {
    const float* det = (const float*)d_in[0];
    const float* p0  = (const float*)d_in[1];
    const float* p1  = (const float*)d_in[2];
    const float* p2  = (const float*)d_in[3];
    const float* p3  = (const float*)d_in[4];
    const float* p4  = (const float*)d_in[5];
    float* out = (float*)d_out;

    k_scores<<<(NDET * 32 + 255) / 256, 256>>>(det);
    k_rank<<<NDET / RPB, 256>>>();
    k_level_sort<<<1, 1024>>>(det);
    k_main<<<TOPK, 256>>>(p0, p1, p2, p3, p4, out);
}

// round 8
// speedup vs baseline: 1.8821x; 1.0322x over previous
#include <cuda_runtime.h>

#define NDET      5000
#define TOPK      1000
#define NCLS      80
#define DETSTRIDE 84
#define CH        256
#define CROP      14

// Scratch (no allocations allowed in kernel_launch)
__device__ float g_scores[NDET];
__device__ int   g_sel[TOPK];            // rank -> original detection row
__device__ float4 g_boxes[TOPK];         // boxes after stable level sort
__device__ int    g_level[TOPK];

// ---------------------------------------------------------------------------
// K1: per-row max over 80 class scores. Warp per row, coalesced reads.
// ---------------------------------------------------------------------------
__global__ void __launch_bounds__(256) k_scores(const float* __restrict__ det) {
    int warp = (blockIdx.x * blockDim.x + threadIdx.x) >> 5;
    int lane = threadIdx.x & 31;
    if (warp >= NDET) return;
    const float* p = det + (size_t)warp * DETSTRIDE + 4;
    float m = -3.402823466e+38f;
    for (int i = lane; i < NCLS; i += 32) m = fmaxf(m, p[i]);
#pragma unroll
    for (int off = 16; off > 0; off >>= 1)
        m = fmaxf(m, __shfl_xor_sync(0xffffffffu, m, off));
    if (lane == 0) g_scores[warp] = m;
}

// ---------------------------------------------------------------------------
// K2: exact jax.lax.top_k via rank counting. 8 rows per block (5000/8 = 625
// blocks, exact), scores staged in shared once; 512 threads split compares.
// ---------------------------------------------------------------------------
#define RPB 8
__global__ void __launch_bounds__(512) k_rank() {
    __shared__ float s[NDET];
    __shared__ int blockcnt[RPB];
    int tid = threadIdx.x;
    for (int j = tid; j < NDET; j += 512) s[j] = g_scores[j];
    if (tid < RPB) blockcnt[tid] = 0;
    __syncthreads();

    int base = blockIdx.x * RPB;
    float sr[RPB];
#pragma unroll
    for (int k = 0; k < RPB; k++) sr[k] = s[base + k];

    int cnt[RPB];
#pragma unroll
    for (int k = 0; k < RPB; k++) cnt[k] = 0;

    for (int j = tid; j < NDET; j += 512) {
        float sj = s[j];
#pragma unroll
        for (int k = 0; k < RPB; k++)
            cnt[k] += (sj > sr[k] || (sj == sr[k] && j < base + k)) ? 1 : 0;
    }
#pragma unroll
    for (int k = 0; k < RPB; k++) {
#pragma unroll
        for (int off = 16; off > 0; off >>= 1)
            cnt[k] += __shfl_down_sync(0xffffffffu, cnt[k], off);
    }
    if ((tid & 31) == 0) {
#pragma unroll
        for (int k = 0; k < RPB; k++) atomicAdd(&blockcnt[k], cnt[k]);
    }
    __syncthreads();
    if (tid < RPB) {
        int rank = blockcnt[tid];
        if (rank < TOPK) g_sel[rank] = base + tid;
    }
}

// ---------------------------------------------------------------------------
// K3: fused level computation + stable counting sort by level (single block).
// ---------------------------------------------------------------------------
__global__ void __launch_bounds__(1024) k_level_sort(const float* __restrict__ det) {
    int r = threadIdx.x;
    float x1 = 0, y1 = 0, x2 = 0, y2 = 0;
    int lev = 0;
    unsigned long long onehot = 0ULL;
    if (r < TOPK) {
        const float* p = det + (size_t)g_sel[r] * DETSTRIDE;
        x1 = p[0]; y1 = p[1]; x2 = p[2]; y2 = p[3];
        float size = sqrtf((x2 - x1) * (y2 - y1));
        float lv = floorf(1.0f + log2f(size / 224.0f + 1e-7f));
        lv = fminf(fmaxf(lv, 0.0f), 4.0f);
        lev = (int)lv;
        onehot = 1ULL << (10 * lev);
    }
    unsigned long long v = onehot;
    int lane = r & 31;
#pragma unroll
    for (int off = 1; off < 32; off <<= 1) {
        unsigned long long n = __shfl_up_sync(0xffffffffu, v, off);
        if (lane >= off) v += n;
    }
    __shared__ unsigned long long warpsum[32];
    int wid = r >> 5;
    if (lane == 31) warpsum[wid] = v;
    __syncthreads();
    if (r < 32) {
        unsigned long long w = warpsum[r];
#pragma unroll
        for (int off = 1; off < 32; off <<= 1) {
            unsigned long long n = __shfl_up_sync(0xffffffffu, w, off);
            if (r >= off) w += n;
        }
        warpsum[r] = w;
    }
    __syncthreads();
    unsigned long long incl = v + (wid > 0 ? warpsum[wid - 1] : 0ULL);
    unsigned long long total = warpsum[31];
    unsigned long long excl = incl - onehot;
    if (r < TOPK) {
        int before = 0;
#pragma unroll
        for (int l = 0; l < 4; l++)
            if (l < lev) before += (int)((total >> (10 * l)) & 1023ULL);
        int pos = before + (int)((excl >> (10 * lev)) & 1023ULL);
        g_boxes[pos] = make_float4(x1, y1, x2, y2);
        g_level[pos] = lev;
    }
}

// ---------------------------------------------------------------------------
// K4: crop_and_resize. 128-thread block = (box, y-half): finer scheduling
// granularity (2000 blocks) + up to 8 blocks/SM. Valid x-columns compacted
// into shared list; hot loop branchless, 2 points/iter (8 indep LDG.128).
// ---------------------------------------------------------------------------
__global__ void __launch_bounds__(128, 8) k_main(
    const float* __restrict__ p0, const float* __restrict__ p1,
    const float* __restrict__ p2, const float* __restrict__ p3,
    const float* __restrict__ p4, float* __restrict__ out)
{
    __shared__ float s_lx[CROP], s_ly[CROP];
    __shared__ int   s_x0[CROP], s_x1[CROP];   // float4 offsets within a row
    __shared__ int   s_r0[CROP], s_r1[CROP];   // float4 offsets of rows
    __shared__ int   s_vx[CROP], s_vy[CROP];
    __shared__ int   s_xlist[CROP], s_xinv[CROP];
    __shared__ int   s_nx, s_ninv;

    int b    = blockIdx.x >> 1;
    int half = blockIdx.x & 1;
    float4 box = g_boxes[b];
    int lev = g_level[b];

    const float* feat;
    int S;
    switch (lev) {
        case 0:  feat = p0; S = 256; break;
        case 1:  feat = p1; S = 128; break;
        case 2:  feat = p2; S = 64;  break;
        case 3:  feat = p3; S = 32;  break;
        default: feat = p4; S = 16;  break;
    }
    float hf = (float)(S - 1);

    if (threadIdx.x < 2 * CROP) {
        int i = threadIdx.x;
        bool isy = i >= CROP;
        int k = isy ? i - CROP : i;
        float a1 = isy ? box.y : box.x;
        float a2 = isy ? box.w : box.z;
        // reference normalizes then rescales by the same (S-1) factor
        float n1 = a1 / hf, n2 = a2 / hf;
        float t = (float)k / 13.0f;
        float s = (n1 + (n2 - n1) * t) * hf;
        int valid = (s >= 0.0f && s <= hf) ? 1 : 0;
        float f0 = floorf(s);
        float l = s - f0;
        int i0 = (int)fminf(fmaxf(f0, 0.0f), hf);
        int i1 = (int)fminf(fmaxf(f0 + 1.0f, 0.0f), hf);
        if (isy) {
            s_ly[k] = l; s_vy[k] = valid;
            s_r0[k] = i0 * S * (CH / 4);
            s_r1[k] = i1 * S * (CH / 4);
        } else {
            s_lx[k] = l; s_vx[k] = valid;
            s_x0[k] = i0 * (CH / 4);
            s_x1[k] = i1 * (CH / 4);
        }
    }
    __syncthreads();
    if (threadIdx.x == 0) {
        int n = 0, m = 0;
#pragma unroll
        for (int i = 0; i < CROP; i++) {
            if (s_vx[i]) s_xlist[n++] = i;
            else         s_xinv[m++]  = i;
        }
        s_nx = n; s_ninv = m;
    }
    __syncthreads();

    int cg = threadIdx.x & 63;   // channel group (float4)
    int rg = threadIdx.x >> 6;   // row group (0..1)
    const float4* fp = (const float4*)feat;
    const float4 zero4 = make_float4(0.f, 0.f, 0.f, 0.f);
    int nv = s_nx, ni = s_ninv;

    int ybase = half * 7;        // rows [ybase, ybase+7)
    for (int yi = ybase + rg; yi < ybase + 7; yi += 2) {
        float4* orow = (float4*)(out + (((size_t)b * CROP + yi) * CROP) * CH) + cg;

        if (!s_vy[yi]) {
#pragma unroll
            for (int xi = 0; xi < CROP; xi++)
                __stcs(orow + (size_t)xi * 64, zero4);
            continue;
        }

        // zero-fill invalid columns (no loads)
        for (int k = 0; k < ni; k++)
            __stcs(orow + (size_t)s_xinv[k] * 64, zero4);

        int r0 = s_r0[yi] + cg;
        int r1 = s_r1[yi] + cg;
        float ly = s_ly[yi];

        int j = 0;
        for (; j + 2 <= nv; j += 2) {
            int xa = s_xlist[j];
            int xb = s_xlist[j + 1];
            int a0 = s_x0[xa], a1 = s_x1[xa];
            int b0i = s_x0[xb], b1i = s_x1[xb];
            float lxa = s_lx[xa], lxb = s_lx[xb];

            float4 A00 = __ldg(fp + r0 + a0);
            float4 A01 = __ldg(fp + r0 + a1);
            float4 A10 = __ldg(fp + r1 + a0);
            float4 A11 = __ldg(fp + r1 + a1);
            float4 B00 = __ldg(fp + r0 + b0i);
            float4 B01 = __ldg(fp + r0 + b1i);
            float4 B10 = __ldg(fp + r1 + b0i);
            float4 B11 = __ldg(fp + r1 + b1i);

            float4 va, vb;
            {
                float t, bo;
                t = A00.x + (A01.x - A00.x) * lxa; bo = A10.x + (A11.x - A10.x) * lxa; va.x = t + (bo - t) * ly;
                t = A00.y + (A01.y - A00.y) * lxa; bo = A10.y + (A11.y - A10.y) * lxa; va.y = t + (bo - t) * ly;
                t = A00.z + (A01.z - A00.z) * lxa; bo = A10.z + (A11.z - A10.z) * lxa; va.z = t + (bo - t) * ly;
                t = A00.w + (A01.w - A00.w) * lxa; bo = A10.w + (A11.w - A10.w) * lxa; va.w = t + (bo - t) * ly;
                t = B00.x + (B01.x - B00.x) * lxb; bo = B10.x + (B11.x - B10.x) * lxb; vb.x = t + (bo - t) * ly;
                t = B00.y + (B01.y - B00.y) * lxb; bo = B10.y + (B11.y - B10.y) * lxb; vb.y = t + (bo - t) * ly;
                t = B00.z + (B01.z - B00.z) * lxb; bo = B10.z + (B11.z - B10.z) * lxb; vb.z = t + (bo - t) * ly;
                t = B00.w + (B01.w - B00.w) * lxb; bo = B10.w + (B11.w - B10.w) * lxb; vb.w = t + (bo - t) * ly;
            }
            __stcs(orow + (size_t)xa * 64, va);
            __stcs(orow + (size_t)xb * 64, vb);
        }
        if (j < nv) {
            int xa = s_xlist[j];
            int a0 = s_x0[xa], a1 = s_x1[xa];
            float lxa = s_lx[xa];
            float4 A00 = __ldg(fp + r0 + a0);
            float4 A01 = __ldg(fp + r0 + a1);
            float4 A10 = __ldg(fp + r1 + a0);
            float4 A11 = __ldg(fp + r1 + a1);
            float4 va;
            float t, bo;
            t = A00.x + (A01.x - A00.x) * lxa; bo = A10.x + (A11.x - A10.x) * lxa; va.x = t + (bo - t) * ly;
            t = A00.y + (A01.y - A00.y) * lxa; bo = A10.y + (A11.y - A10.y) * lxa; va.y = t + (bo - t) * ly;
            t = A00.z + (A01.z - A00.z) * lxa; bo = A10.z + (A11.z - A10.z) * lxa; va.z = t + (bo - t) * ly;
            t = A00.w + (A01.w - A00.w) * lxa; bo = A10.w + (A11.w - A10.w) * lxa; va.w = t + (bo - t) * ly;
            __stcs(orow + (size_t)xa * 64, va);
        }
    }
}

// ---------------------------------------------------------------------------
extern "C" void kernel_launch(void* const* d_in, const int* in_sizes, int n_in,
                              void* d_out, int out_size) {
    const float* det = (const float*)d_in[0];
    const float* p0  = (const float*)d_in[1];
    const float* p1  = (const float*)d_in[2];
    const float* p2  = (const float*)d_in[3];
    const float* p3  = (const float*)d_in[4];
    const float* p4  = (const float*)d_in[5];
    float* out = (float*)d_out;

    k_scores<<<(NDET * 32 + 255) / 256, 256>>>(det);
    k_rank<<<NDET / RPB, 512>>>();
    k_level_sort<<<1, 1024>>>(det);
    k_main<<<TOPK * 2, 128>>>(p0, p1, p2, p3, p4, out);
}

// round 10
// speedup vs baseline: 1.9438x; 1.0328x over previous
#include <cuda_runtime.h>

#define NDET      5000
#define TOPK      1000
#define NCLS      80
#define DETSTRIDE 84
#define CH        256
#define CROP      14

// Scratch (no allocations allowed in kernel_launch)
__device__ float g_scores[NDET];
__device__ int   g_sel[TOPK];            // rank -> original detection row
__device__ float4 g_boxes[TOPK];         // boxes after stable level sort
__device__ int    g_level[TOPK];

// ---------------------------------------------------------------------------
// K1: per-row max over 80 class scores. Warp per row, coalesced reads.
// ---------------------------------------------------------------------------
__global__ void __launch_bounds__(256) k_scores(const float* __restrict__ det) {
    int warp = (blockIdx.x * blockDim.x + threadIdx.x) >> 5;
    int lane = threadIdx.x & 31;
    if (warp >= NDET) return;
    const float* p = det + (size_t)warp * DETSTRIDE + 4;
    float m = -3.402823466e+38f;
    for (int i = lane; i < NCLS; i += 32) m = fmaxf(m, p[i]);
#pragma unroll
    for (int off = 16; off > 0; off >>= 1)
        m = fmaxf(m, __shfl_xor_sync(0xffffffffu, m, off));
    if (lane == 0) g_scores[warp] = m;
}

// ---------------------------------------------------------------------------
// K2: exact jax.lax.top_k via rank counting. 8 rows per block (5000/8 = 625
// blocks, exact), scores staged in shared once; 512 threads split compares.
// ---------------------------------------------------------------------------
#define RPB 8
__global__ void __launch_bounds__(512) k_rank() {
    __shared__ float s[NDET];
    __shared__ int blockcnt[RPB];
    int tid = threadIdx.x;
    for (int j = tid; j < NDET; j += 512) s[j] = g_scores[j];
    if (tid < RPB) blockcnt[tid] = 0;
    __syncthreads();

    int base = blockIdx.x * RPB;
    float sr[RPB];
#pragma unroll
    for (int k = 0; k < RPB; k++) sr[k] = s[base + k];

    int cnt[RPB];
#pragma unroll
    for (int k = 0; k < RPB; k++) cnt[k] = 0;

    for (int j = tid; j < NDET; j += 512) {
        float sj = s[j];
#pragma unroll
        for (int k = 0; k < RPB; k++)
            cnt[k] += (sj > sr[k] || (sj == sr[k] && j < base + k)) ? 1 : 0;
    }
#pragma unroll
    for (int k = 0; k < RPB; k++) {
#pragma unroll
        for (int off = 16; off > 0; off >>= 1)
            cnt[k] += __shfl_down_sync(0xffffffffu, cnt[k], off);
    }
    if ((tid & 31) == 0) {
#pragma unroll
        for (int k = 0; k < RPB; k++) atomicAdd(&blockcnt[k], cnt[k]);
    }
    __syncthreads();
    if (tid < RPB) {
        int rank = blockcnt[tid];
        if (rank < TOPK) g_sel[rank] = base + tid;
    }
}

// ---------------------------------------------------------------------------
// K3: fused level computation + stable counting sort by level (single block).
// ---------------------------------------------------------------------------
__global__ void __launch_bounds__(1024) k_level_sort(const float* __restrict__ det) {
    int r = threadIdx.x;
    float x1 = 0, y1 = 0, x2 = 0, y2 = 0;
    int lev = 0;
    unsigned long long onehot = 0ULL;
    if (r < TOPK) {
        const float* p = det + (size_t)g_sel[r] * DETSTRIDE;
        x1 = p[0]; y1 = p[1]; x2 = p[2]; y2 = p[3];
        float size = sqrtf((x2 - x1) * (y2 - y1));
        float lv = floorf(1.0f + log2f(size / 224.0f + 1e-7f));
        lv = fminf(fmaxf(lv, 0.0f), 4.0f);
        lev = (int)lv;
        onehot = 1ULL << (10 * lev);
    }
    unsigned long long v = onehot;
    int lane = r & 31;
#pragma unroll
    for (int off = 1; off < 32; off <<= 1) {
        unsigned long long n = __shfl_up_sync(0xffffffffu, v, off);
        if (lane >= off) v += n;
    }
    __shared__ unsigned long long warpsum[32];
    int wid = r >> 5;
    if (lane == 31) warpsum[wid] = v;
    __syncthreads();
    if (r < 32) {
        unsigned long long w = warpsum[r];
#pragma unroll
        for (int off = 1; off < 32; off <<= 1) {
            unsigned long long n = __shfl_up_sync(0xffffffffu, w, off);
            if (r >= off) w += n;
        }
        warpsum[r] = w;
    }
    __syncthreads();
    unsigned long long incl = v + (wid > 0 ? warpsum[wid - 1] : 0ULL);
    unsigned long long total = warpsum[31];
    unsigned long long excl = incl - onehot;
    if (r < TOPK) {
        int before = 0;
#pragma unroll
        for (int l = 0; l < 4; l++)
            if (l < lev) before += (int)((total >> (10 * l)) & 1023ULL);
        int pos = before + (int)((excl >> (10 * lev)) & 1023ULL);
        g_boxes[pos] = make_float4(x1, y1, x2, y2);
        g_level[pos] = lev;
    }
}

// ---------------------------------------------------------------------------
// K4: crop_and_resize. 128-thread block = (box, y-half), fixed grid 2000.
// Valid x-columns compacted + padded to multiple of 4; hot loop does
// 4 points/iter = 16 independent LDG.128 per thread for high MLP.
// ---------------------------------------------------------------------------
__global__ void __launch_bounds__(128, 5) k_main(
    const float* __restrict__ p0, const float* __restrict__ p1,
    const float* __restrict__ p2, const float* __restrict__ p3,
    const float* __restrict__ p4, float* __restrict__ out)
{
    __shared__ float s_lx[CROP], s_ly[CROP];
    __shared__ int   s_x0[CROP], s_x1[CROP];   // float4 offsets within a row
    __shared__ int   s_r0[CROP], s_r1[CROP];   // float4 offsets of rows
    __shared__ int   s_vx[CROP], s_vy[CROP];
    __shared__ int   s_xlist[CROP + 3], s_xinv[CROP];
    __shared__ int   s_nx, s_ninv;

    int tid  = threadIdx.x;
    int b    = blockIdx.x >> 1;
    int half = blockIdx.x & 1;
    float4 box = g_boxes[b];
    int lev = g_level[b];

    const float* feat;
    int S;
    switch (lev) {
        case 0:  feat = p0; S = 256; break;
        case 1:  feat = p1; S = 128; break;
        case 2:  feat = p2; S = 64;  break;
        case 3:  feat = p3; S = 32;  break;
        default: feat = p4; S = 16;  break;
    }
    float hf = (float)(S - 1);

    if (tid < 2 * CROP) {
        int i = tid;
        bool isy = i >= CROP;
        int k = isy ? i - CROP : i;
        float a1 = isy ? box.y : box.x;
        float a2 = isy ? box.w : box.z;
        // reference normalizes then rescales by the same (S-1) factor
        float n1 = a1 / hf, n2 = a2 / hf;
        float t = (float)k / 13.0f;
        float s = (n1 + (n2 - n1) * t) * hf;
        int valid = (s >= 0.0f && s <= hf) ? 1 : 0;
        float f0 = floorf(s);
        float l = s - f0;
        int i0 = (int)fminf(fmaxf(f0, 0.0f), hf);
        int i1 = (int)fminf(fmaxf(f0 + 1.0f, 0.0f), hf);
        if (isy) {
            s_ly[k] = l; s_vy[k] = valid;
            s_r0[k] = i0 * S * (CH / 4);
            s_r1[k] = i1 * S * (CH / 4);
        } else {
            s_lx[k] = l; s_vx[k] = valid;
            s_x0[k] = i0 * (CH / 4);
            s_x1[k] = i1 * (CH / 4);
        }
    }
    __syncthreads();
    if (tid == 0) {
        int n = 0, m = 0;
#pragma unroll
        for (int i = 0; i < CROP; i++) {
            if (s_vx[i]) s_xlist[n++] = i;
            else         s_xinv[m++]  = i;
        }
        s_nx = n; s_ninv = m;
        if (n > 0) {                      // pad to multiple of 4
            int last = s_xlist[n - 1];
            while (n & 3) s_xlist[n++] = last;
        }
    }
    __syncthreads();

    int cg = tid & 63;           // channel group (float4)
    int rg = tid >> 6;           // row group (0..1)
    const float4* fp = (const float4*)feat;
    const float4 zero4 = make_float4(0.f, 0.f, 0.f, 0.f);
    int nv = s_nx, ni = s_ninv;
    int nvp = (nv + 3) & ~3;
    int ybase = half * 7;        // rows [ybase, ybase+7)

    for (int yi = ybase + rg; yi < ybase + 7; yi += 2) {
        float4* orow = (float4*)(out + (((size_t)b * CROP + yi) * CROP) * CH) + cg;

        if (!s_vy[yi]) {
#pragma unroll
            for (int xi = 0; xi < CROP; xi++)
                __stcs(orow + (size_t)xi * 64, zero4);
            continue;
        }

        // zero-fill invalid columns (no loads)
        for (int k = 0; k < ni; k++)
            __stcs(orow + (size_t)s_xinv[k] * 64, zero4);

        int r0 = s_r0[yi] + cg;
        int r1 = s_r1[yi] + cg;
        float ly = s_ly[yi];

        for (int j = 0; j < nvp; j += 4) {
            int   xq[4];
            int   q0[4], q1[4];
            float lx[4];
#pragma unroll
            for (int q = 0; q < 4; q++) {
                xq[q] = s_xlist[j + q];
                q0[q] = s_x0[xq[q]];
                q1[q] = s_x1[xq[q]];
                lx[q] = s_lx[xq[q]];
            }
            float4 F00[4], F01[4], F10[4], F11[4];
#pragma unroll
            for (int q = 0; q < 4; q++) {
                F00[q] = __ldg(fp + r0 + q0[q]);
                F01[q] = __ldg(fp + r0 + q1[q]);
                F10[q] = __ldg(fp + r1 + q0[q]);
                F11[q] = __ldg(fp + r1 + q1[q]);
            }
#pragma unroll
            for (int q = 0; q < 4; q++) {
                float4 v;
                float t, bo;
                t = F00[q].x + (F01[q].x - F00[q].x) * lx[q];
                bo = F10[q].x + (F11[q].x - F10[q].x) * lx[q];
                v.x = t + (bo - t) * ly;
                t = F00[q].y + (F01[q].y - F00[q].y) * lx[q];
                bo = F10[q].y + (F11[q].y - F10[q].y) * lx[q];
                v.y = t + (bo - t) * ly;
                t = F00[q].z + (F01[q].z - F00[q].z) * lx[q];
                bo = F10[q].z + (F11[q].z - F10[q].z) * lx[q];
                v.z = t + (bo - t) * ly;
                t = F00[q].w + (F01[q].w - F00[q].w) * lx[q];
                bo = F10[q].w + (F11[q].w - F10[q].w) * lx[q];
                v.w = t + (bo - t) * ly;
                __stcs(orow + (size_t)xq[q] * 64, v);
            }
        }
    }
}

// ---------------------------------------------------------------------------
extern "C" void kernel_launch(void* const* d_in, const int* in_sizes, int n_in,
                              void* d_out, int out_size) {
    const float* det = (const float*)d_in[0];
    const float* p0  = (const float*)d_in[1];
    const float* p1  = (const float*)d_in[2];
    const float* p2  = (const float*)d_in[3];
    const float* p3  = (const float*)d_in[4];
    const float* p4  = (const float*)d_in[5];
    float* out = (float*)d_out;

    k_scores<<<(NDET * 32 + 255) / 256, 256>>>(det);
    k_rank<<<NDET / RPB, 512>>>();
    k_level_sort<<<1, 1024>>>(det);
    k_main<<<TOPK * 2, 128>>>(p0, p1, p2, p3, p4, out);
}